// round 6
// baseline (speedup 1.0000x reference)
#include <cuda_runtime.h>
#include <cuda_bf16.h>

#define N 1024
#define D 128
#define H 128
#define MAIN_GRID 148

// Scratch (allocation-free rule: __device__ globals)
__device__ __align__(16) float g_v[D];   // reduced v
__device__ float g_nb[N];                // node_part[j] + consts
__device__ int   g_row_ctr;              // work-steal counter (seeded by prologue)

// ---------------------------------------------------------------------------
// Prologue (fused setup + nodepart). 128 blocks x 1024 threads.
// Thread (g,d): g = tid>>7 in 0..7 covers h in [g*16,g*16+16) -> only 48
// loads/thread (vs 192 in R5), shared-reduced. Warps 0..7 then compute
// nb[j] for the block's 8 rows. Block 0 materializes g_v and seeds the
// main kernel's work-steal counter (deterministic per launch/replay).
// ---------------------------------------------------------------------------
__global__ void __launch_bounds__(1024, 1)
prologue_kernel(const float* __restrict__ node_feat,
                const float* __restrict__ Wh,
                const float* __restrict__ bh,
                const float* __restrict__ Wt,
                const float* __restrict__ bt,
                const float* __restrict__ Wr,
                const float* __restrict__ br,
                const float* __restrict__ wt_w,
                const float* __restrict__ wt_b) {
    const int tid  = threadIdx.x;
    const int d    = tid & 127;
    const int g    = tid >> 7;      // 0..7
    const int lane = tid & 31;
    const int w    = tid >> 5;      // warp 0..31

    __shared__ float su[8][128];
    __shared__ float sv[8][128];
    __shared__ float sconsts;

    float u = 0.f, v = 0.f;
    const int h0 = g * 16;
    #pragma unroll
    for (int k = 0; k < 16; ++k) {
        int h = h0 + k;
        float w1 = __ldg(&wt_w[h]);
        float w2 = __ldg(&wt_w[H + h]);
        float w3 = __ldg(&wt_w[2 * H + h]);
        u = fmaf(__ldg(&Wh[h * D + d]), w1, u);
        u = fmaf(__ldg(&Wt[h * D + d]), w2, u);
        v = fmaf(__ldg(&Wr[h * D + d]), w3, v);
    }
    su[g][d] = u;
    sv[g][d] = v;

    // consts by warp 0
    if (tid < 32) {
        float c = 0.f;
        #pragma unroll
        for (int h = lane; h < H; h += 32) {
            c += bh[h] * __ldg(&wt_w[h]) + bt[h] * __ldg(&wt_w[H + h]) +
                 br[h] * __ldg(&wt_w[2 * H + h]);
        }
        #pragma unroll
        for (int o = 16; o > 0; o >>= 1) c += __shfl_xor_sync(0xffffffffu, c, o);
        if (lane == 0) sconsts = c + __ldg(&wt_b[0]);
    }
    __syncthreads();

    if (blockIdx.x == 0) {
        if (tid < 128) {
            float vv = 0.f;
            #pragma unroll
            for (int gg = 0; gg < 8; ++gg) vv += sv[gg][tid];
            g_v[tid] = vv;
        }
        if (tid == 0) g_row_ctr = MAIN_GRID;   // seed work-steal counter
    }

    // warps 0..7: nb[j] for j = blk*8 + w
    if (w < 8) {
        const int j = blockIdx.x * 8 + w;
        float4 u4 = make_float4(0.f, 0.f, 0.f, 0.f);
        #pragma unroll
        for (int gg = 0; gg < 8; ++gg) {
            float4 p = reinterpret_cast<const float4*>(su[gg])[lane];
            u4.x += p.x; u4.y += p.y; u4.z += p.z; u4.w += p.w;
        }
        float4 x = reinterpret_cast<const float4*>(node_feat + (size_t)j * D)[lane];
        float dsum = x.x * u4.x + x.y * u4.y + x.z * u4.z + x.w * u4.w;
        #pragma unroll
        for (int o = 16; o > 0; o >>= 1)
            dsum += __shfl_xor_sync(0xffffffffu, dsum, o);
        if (lane == 0) g_nb[j] = dsum + sconsts;
    }
}

// ---------------------------------------------------------------------------
// Main: persistent streaming + single-pass softmax.
// 148 blocks x 1024 threads, one per SM, rows grabbed via atomic counter
// (no wave transitions; g_v loaded once per block). Per row: warp w owns
// j in [w*32, w*32+32), unroll 8. sp double-buffered so consecutive rows
// need no extra barrier. Next-row index is read between the two epilogue
// barriers (write-before-B1 / read-before-B2 ordering).
// ---------------------------------------------------------------------------
__global__ void __launch_bounds__(1024, 1)
main_kernel(const float* __restrict__ edge_feat, float* __restrict__ out) {
    const int tid  = threadIdx.x;
    const int lane = tid & 31;
    const int w    = tid >> 5;

    __shared__ float sp[2][N];
    __shared__ float sred[32];
    __shared__ float s_bcast;
    __shared__ int   s_next;

    const float4 v4 = reinterpret_cast<const float4*>(g_v)[lane];
    const int j0 = w << 5;

    int row = blockIdx.x;
    int buf = 0;

    while (row < N) {
        // prefetch the next row index early (hidden under the stream)
        if (tid == 0) s_next = atomicAdd(&g_row_ctr, 1);

        const float4* base =
            reinterpret_cast<const float4*>(edge_feat + (size_t)row * N * D);
        float* spb = sp[buf];

        float wsum = 0.f;
        #pragma unroll
        for (int k = 0; k < 32; k += 8) {
            float4 x0 = __ldcs(&base[(size_t)(j0 + k + 0) * (D / 4) + lane]);
            float4 x1 = __ldcs(&base[(size_t)(j0 + k + 1) * (D / 4) + lane]);
            float4 x2 = __ldcs(&base[(size_t)(j0 + k + 2) * (D / 4) + lane]);
            float4 x3 = __ldcs(&base[(size_t)(j0 + k + 3) * (D / 4) + lane]);
            float4 x4 = __ldcs(&base[(size_t)(j0 + k + 4) * (D / 4) + lane]);
            float4 x5 = __ldcs(&base[(size_t)(j0 + k + 5) * (D / 4) + lane]);
            float4 x6 = __ldcs(&base[(size_t)(j0 + k + 6) * (D / 4) + lane]);
            float4 x7 = __ldcs(&base[(size_t)(j0 + k + 7) * (D / 4) + lane]);
            float d0 = x0.x * v4.x + x0.y * v4.y + x0.z * v4.z + x0.w * v4.w;
            float d1 = x1.x * v4.x + x1.y * v4.y + x1.z * v4.z + x1.w * v4.w;
            float d2 = x2.x * v4.x + x2.y * v4.y + x2.z * v4.z + x2.w * v4.w;
            float d3 = x3.x * v4.x + x3.y * v4.y + x3.z * v4.z + x3.w * v4.w;
            float d4 = x4.x * v4.x + x4.y * v4.y + x4.z * v4.z + x4.w * v4.w;
            float d5 = x5.x * v4.x + x5.y * v4.y + x5.z * v4.z + x5.w * v4.w;
            float d6 = x6.x * v4.x + x6.y * v4.y + x6.z * v4.z + x6.w * v4.w;
            float d7 = x7.x * v4.x + x7.y * v4.y + x7.z * v4.z + x7.w * v4.w;
            #pragma unroll
            for (int o = 16; o > 0; o >>= 1) {
                d0 += __shfl_xor_sync(0xffffffffu, d0, o);
                d1 += __shfl_xor_sync(0xffffffffu, d1, o);
                d2 += __shfl_xor_sync(0xffffffffu, d2, o);
                d3 += __shfl_xor_sync(0xffffffffu, d3, o);
                d4 += __shfl_xor_sync(0xffffffffu, d4, o);
                d5 += __shfl_xor_sync(0xffffffffu, d5, o);
                d6 += __shfl_xor_sync(0xffffffffu, d6, o);
                d7 += __shfl_xor_sync(0xffffffffu, d7, o);
            }
            if (lane == 0) {
                float p0 = __expf(d0 + __ldg(&g_nb[j0 + k + 0]));
                float p1 = __expf(d1 + __ldg(&g_nb[j0 + k + 1]));
                float p2 = __expf(d2 + __ldg(&g_nb[j0 + k + 2]));
                float p3 = __expf(d3 + __ldg(&g_nb[j0 + k + 3]));
                float p4 = __expf(d4 + __ldg(&g_nb[j0 + k + 4]));
                float p5 = __expf(d5 + __ldg(&g_nb[j0 + k + 5]));
                float p6 = __expf(d6 + __ldg(&g_nb[j0 + k + 6]));
                float p7 = __expf(d7 + __ldg(&g_nb[j0 + k + 7]));
                spb[j0 + k + 0] = p0;
                spb[j0 + k + 1] = p1;
                spb[j0 + k + 2] = p2;
                spb[j0 + k + 3] = p3;
                spb[j0 + k + 4] = p4;
                spb[j0 + k + 5] = p5;
                spb[j0 + k + 6] = p6;
                spb[j0 + k + 7] = p7;
                wsum += ((p0 + p1) + (p2 + p3)) + ((p4 + p5) + (p6 + p7));
            }
        }
        if (lane == 0) sred[w] = wsum;
        __syncthreads();                 // B1

        const int nrow = s_next;         // read between B1 and B2 (safe)
        if (w == 0) {
            float ss = sred[lane];
            #pragma unroll
            for (int o = 16; o > 0; o >>= 1)
                ss += __shfl_xor_sync(0xffffffffu, ss, o);
            if (lane == 0) s_bcast = ss;
        }
        __syncthreads();                 // B2

        out[(size_t)row * N + tid] = spb[tid] * (1.0f / s_bcast);

        row = nrow;
        buf ^= 1;
    }
}

// ---------------------------------------------------------------------------
// Launcher. Input order per metadata:
// 0 node_feat (N,D) f32 | 1 edge_feat (N,N,D) f32 | 2 mask (unused)
// 3 Wh | 4 bh | 5 Wt | 6 bt | 7 Wr | 8 br | 9 wt_w | 10 wt_b
// ---------------------------------------------------------------------------
extern "C" void kernel_launch(void* const* d_in, const int* in_sizes, int n_in,
                              void* d_out, int out_size) {
    const float* node_feat = (const float*)d_in[0];
    const float* edge_feat = (const float*)d_in[1];
    const float* Wh   = (const float*)d_in[3];
    const float* bh   = (const float*)d_in[4];
    const float* Wt   = (const float*)d_in[5];
    const float* bt   = (const float*)d_in[6];
    const float* Wr   = (const float*)d_in[7];
    const float* br   = (const float*)d_in[8];
    const float* wt_w = (const float*)d_in[9];
    const float* wt_b = (const float*)d_in[10];
    float* out = (float*)d_out;

    prologue_kernel<<<128, 1024>>>(node_feat, Wh, bh, Wt, bt, Wr, br, wt_w, wt_b);
    main_kernel<<<MAIN_GRID, 1024>>>(edge_feat, out);
}

// round 7
// speedup vs baseline: 1.0155x; 1.0155x over previous
#include <cuda_runtime.h>
#include <cuda_bf16.h>

#define N 1024
#define D 128
#define H 128

// Scratch (allocation-free rule: __device__ globals)
__device__ __align__(16) float g_v[D];   // reduced v
__device__ float g_nb[N];                // node_part[j] + consts

// ---------------------------------------------------------------------------
// Prologue (fused setup + nodepart). 128 blocks x 1024 threads.
// Thread (g,d): g = tid>>7 covers h in [g*16,g*16+16) -> 48 loads/thread,
// shared-reduced. Warps 0..7 then compute nb[j] for the block's 8 rows.
// Block 0 materializes g_v.  (R6-verified: ~3.6us incl. launch gap.)
// ---------------------------------------------------------------------------
__global__ void __launch_bounds__(1024, 1)
prologue_kernel(const float* __restrict__ node_feat,
                const float* __restrict__ Wh,
                const float* __restrict__ bh,
                const float* __restrict__ Wt,
                const float* __restrict__ bt,
                const float* __restrict__ Wr,
                const float* __restrict__ br,
                const float* __restrict__ wt_w,
                const float* __restrict__ wt_b) {
    const int tid  = threadIdx.x;
    const int d    = tid & 127;
    const int g    = tid >> 7;      // 0..7
    const int lane = tid & 31;
    const int w    = tid >> 5;      // warp 0..31

    __shared__ float su[8][128];
    __shared__ float sv[8][128];
    __shared__ float sconsts;

    float u = 0.f, v = 0.f;
    const int h0 = g * 16;
    #pragma unroll
    for (int k = 0; k < 16; ++k) {
        int h = h0 + k;
        float w1 = __ldg(&wt_w[h]);
        float w2 = __ldg(&wt_w[H + h]);
        float w3 = __ldg(&wt_w[2 * H + h]);
        u = fmaf(__ldg(&Wh[h * D + d]), w1, u);
        u = fmaf(__ldg(&Wt[h * D + d]), w2, u);
        v = fmaf(__ldg(&Wr[h * D + d]), w3, v);
    }
    su[g][d] = u;
    sv[g][d] = v;

    // consts by warp 0
    if (tid < 32) {
        float c = 0.f;
        #pragma unroll
        for (int h = lane; h < H; h += 32) {
            c += bh[h] * __ldg(&wt_w[h]) + bt[h] * __ldg(&wt_w[H + h]) +
                 br[h] * __ldg(&wt_w[2 * H + h]);
        }
        #pragma unroll
        for (int o = 16; o > 0; o >>= 1) c += __shfl_xor_sync(0xffffffffu, c, o);
        if (lane == 0) sconsts = c + __ldg(&wt_b[0]);
    }
    __syncthreads();

    if (blockIdx.x == 0 && tid < 128) {
        float vv = 0.f;
        #pragma unroll
        for (int gg = 0; gg < 8; ++gg) vv += sv[gg][tid];
        g_v[tid] = vv;
    }

    // warps 0..7: nb[j] for j = blk*8 + w
    if (w < 8) {
        const int j = blockIdx.x * 8 + w;
        float4 u4 = make_float4(0.f, 0.f, 0.f, 0.f);
        #pragma unroll
        for (int gg = 0; gg < 8; ++gg) {
            float4 p = reinterpret_cast<const float4*>(su[gg])[lane];
            u4.x += p.x; u4.y += p.y; u4.z += p.z; u4.w += p.w;
        }
        float4 x = reinterpret_cast<const float4*>(node_feat + (size_t)j * D)[lane];
        float dsum = x.x * u4.x + x.y * u4.y + x.z * u4.z + x.w * u4.w;
        #pragma unroll
        for (int o = 16; o > 0; o >>= 1)
            dsum += __shfl_xor_sync(0xffffffffu, dsum, o);
        if (lane == 0) g_nb[j] = dsum + sconsts;
    }
}

// ---------------------------------------------------------------------------
// Main: R5-verified shape (81.9us @ 83.6% DRAM). One block per row, 1024
// threads, 1 block/SM, CLC handles block replacement (hardware overlap of
// row boundaries -- beats software persistence, proven in R6).
// Warp w owns j in [w*32, w*32+32), unroll 8 -> 8 independent LDG.128 per
// lane in flight. Single-pass softmax (energies bounded; shift-invariant):
// lane 0 computes exp + warp partial sum during the stream; epilogue is one
// 32-value reduce (2 barriers).
// ---------------------------------------------------------------------------
__global__ void __launch_bounds__(1024, 1)
main_kernel(const float* __restrict__ edge_feat, float* __restrict__ out) {
    const int i    = blockIdx.x;
    const int tid  = threadIdx.x;
    const int lane = tid & 31;
    const int w    = tid >> 5;

    __shared__ float sp[N];      // exp(energy)
    __shared__ float sred[32];
    __shared__ float s_bcast;

    const float4 v4 = reinterpret_cast<const float4*>(g_v)[lane];
    const float4* base =
        reinterpret_cast<const float4*>(edge_feat + (size_t)i * N * D);

    const int j0 = w << 5;
    float wsum = 0.f;
    #pragma unroll
    for (int k = 0; k < 32; k += 8) {
        float4 x0 = __ldcs(&base[(size_t)(j0 + k + 0) * (D / 4) + lane]);
        float4 x1 = __ldcs(&base[(size_t)(j0 + k + 1) * (D / 4) + lane]);
        float4 x2 = __ldcs(&base[(size_t)(j0 + k + 2) * (D / 4) + lane]);
        float4 x3 = __ldcs(&base[(size_t)(j0 + k + 3) * (D / 4) + lane]);
        float4 x4 = __ldcs(&base[(size_t)(j0 + k + 4) * (D / 4) + lane]);
        float4 x5 = __ldcs(&base[(size_t)(j0 + k + 5) * (D / 4) + lane]);
        float4 x6 = __ldcs(&base[(size_t)(j0 + k + 6) * (D / 4) + lane]);
        float4 x7 = __ldcs(&base[(size_t)(j0 + k + 7) * (D / 4) + lane]);
        float d0 = x0.x * v4.x + x0.y * v4.y + x0.z * v4.z + x0.w * v4.w;
        float d1 = x1.x * v4.x + x1.y * v4.y + x1.z * v4.z + x1.w * v4.w;
        float d2 = x2.x * v4.x + x2.y * v4.y + x2.z * v4.z + x2.w * v4.w;
        float d3 = x3.x * v4.x + x3.y * v4.y + x3.z * v4.z + x3.w * v4.w;
        float d4 = x4.x * v4.x + x4.y * v4.y + x4.z * v4.z + x4.w * v4.w;
        float d5 = x5.x * v4.x + x5.y * v4.y + x5.z * v4.z + x5.w * v4.w;
        float d6 = x6.x * v4.x + x6.y * v4.y + x6.z * v4.z + x6.w * v4.w;
        float d7 = x7.x * v4.x + x7.y * v4.y + x7.z * v4.z + x7.w * v4.w;
        #pragma unroll
        for (int o = 16; o > 0; o >>= 1) {
            d0 += __shfl_xor_sync(0xffffffffu, d0, o);
            d1 += __shfl_xor_sync(0xffffffffu, d1, o);
            d2 += __shfl_xor_sync(0xffffffffu, d2, o);
            d3 += __shfl_xor_sync(0xffffffffu, d3, o);
            d4 += __shfl_xor_sync(0xffffffffu, d4, o);
            d5 += __shfl_xor_sync(0xffffffffu, d5, o);
            d6 += __shfl_xor_sync(0xffffffffu, d6, o);
            d7 += __shfl_xor_sync(0xffffffffu, d7, o);
        }
        if (lane == 0) {
            float p0 = __expf(d0 + __ldg(&g_nb[j0 + k + 0]));
            float p1 = __expf(d1 + __ldg(&g_nb[j0 + k + 1]));
            float p2 = __expf(d2 + __ldg(&g_nb[j0 + k + 2]));
            float p3 = __expf(d3 + __ldg(&g_nb[j0 + k + 3]));
            float p4 = __expf(d4 + __ldg(&g_nb[j0 + k + 4]));
            float p5 = __expf(d5 + __ldg(&g_nb[j0 + k + 5]));
            float p6 = __expf(d6 + __ldg(&g_nb[j0 + k + 6]));
            float p7 = __expf(d7 + __ldg(&g_nb[j0 + k + 7]));
            sp[j0 + k + 0] = p0;
            sp[j0 + k + 1] = p1;
            sp[j0 + k + 2] = p2;
            sp[j0 + k + 3] = p3;
            sp[j0 + k + 4] = p4;
            sp[j0 + k + 5] = p5;
            sp[j0 + k + 6] = p6;
            sp[j0 + k + 7] = p7;
            wsum += ((p0 + p1) + (p2 + p3)) + ((p4 + p5) + (p6 + p7));
        }
    }
    if (lane == 0) sred[w] = wsum;
    __syncthreads();

    if (w == 0) {
        float ss = sred[lane];
        #pragma unroll
        for (int o = 16; o > 0; o >>= 1)
            ss += __shfl_xor_sync(0xffffffffu, ss, o);
        if (lane == 0) s_bcast = ss;
    }
    __syncthreads();

    out[(size_t)i * N + tid] = sp[tid] * (1.0f / s_bcast);
}

// ---------------------------------------------------------------------------
// Launcher. Input order per metadata:
// 0 node_feat (N,D) f32 | 1 edge_feat (N,N,D) f32 | 2 mask (unused)
// 3 Wh | 4 bh | 5 Wt | 6 bt | 7 Wr | 8 br | 9 wt_w | 10 wt_b
// ---------------------------------------------------------------------------
extern "C" void kernel_launch(void* const* d_in, const int* in_sizes, int n_in,
                              void* d_out, int out_size) {
    const float* node_feat = (const float*)d_in[0];
    const float* edge_feat = (const float*)d_in[1];
    const float* Wh   = (const float*)d_in[3];
    const float* bh   = (const float*)d_in[4];
    const float* Wt   = (const float*)d_in[5];
    const float* bt   = (const float*)d_in[6];
    const float* Wr   = (const float*)d_in[7];
    const float* br   = (const float*)d_in[8];
    const float* wt_w = (const float*)d_in[9];
    const float* wt_b = (const float*)d_in[10];
    float* out = (float*)d_out;

    prologue_kernel<<<128, 1024>>>(node_feat, Wh, bh, Wt, bt, Wr, br, wt_w, wt_b);
    main_kernel<<<N, 1024>>>(edge_feat, out);
}

// round 8
// speedup vs baseline: 1.0402x; 1.0244x over previous
#include <cuda_runtime.h>
#include <cuda_bf16.h>

#define N 1024
#define D 128
#define H 128

// Scratch (allocation-free rule: __device__ globals)
__device__ __align__(16) float g_v[D];   // reduced v
__device__ float g_nb[N];                // node_part[j] + consts

// ---------------------------------------------------------------------------
// Prologue (fused setup + nodepart). 128 blocks x 1024 threads. (verified)
// ---------------------------------------------------------------------------
__global__ void __launch_bounds__(1024, 1)
prologue_kernel(const float* __restrict__ node_feat,
                const float* __restrict__ Wh,
                const float* __restrict__ bh,
                const float* __restrict__ Wt,
                const float* __restrict__ bt,
                const float* __restrict__ Wr,
                const float* __restrict__ br,
                const float* __restrict__ wt_w,
                const float* __restrict__ wt_b) {
    const int tid  = threadIdx.x;
    const int d    = tid & 127;
    const int g    = tid >> 7;      // 0..7
    const int lane = tid & 31;
    const int w    = tid >> 5;      // warp 0..31

    __shared__ float su[8][128];
    __shared__ float sv[8][128];
    __shared__ float sconsts;

    float u = 0.f, v = 0.f;
    const int h0 = g * 16;
    #pragma unroll
    for (int k = 0; k < 16; ++k) {
        int h = h0 + k;
        float w1 = __ldg(&wt_w[h]);
        float w2 = __ldg(&wt_w[H + h]);
        float w3 = __ldg(&wt_w[2 * H + h]);
        u = fmaf(__ldg(&Wh[h * D + d]), w1, u);
        u = fmaf(__ldg(&Wt[h * D + d]), w2, u);
        v = fmaf(__ldg(&Wr[h * D + d]), w3, v);
    }
    su[g][d] = u;
    sv[g][d] = v;

    if (tid < 32) {
        float c = 0.f;
        #pragma unroll
        for (int h = lane; h < H; h += 32) {
            c += bh[h] * __ldg(&wt_w[h]) + bt[h] * __ldg(&wt_w[H + h]) +
                 br[h] * __ldg(&wt_w[2 * H + h]);
        }
        #pragma unroll
        for (int o = 16; o > 0; o >>= 1) c += __shfl_xor_sync(0xffffffffu, c, o);
        if (lane == 0) sconsts = c + __ldg(&wt_b[0]);
    }
    __syncthreads();

    if (blockIdx.x == 0 && tid < 128) {
        float vv = 0.f;
        #pragma unroll
        for (int gg = 0; gg < 8; ++gg) vv += sv[gg][tid];
        g_v[tid] = vv;
    }

    if (w < 8) {
        const int j = blockIdx.x * 8 + w;
        float4 u4 = make_float4(0.f, 0.f, 0.f, 0.f);
        #pragma unroll
        for (int gg = 0; gg < 8; ++gg) {
            float4 p = reinterpret_cast<const float4*>(su[gg])[lane];
            u4.x += p.x; u4.y += p.y; u4.z += p.z; u4.w += p.w;
        }
        float4 x = reinterpret_cast<const float4*>(node_feat + (size_t)j * D)[lane];
        float dsum = x.x * u4.x + x.y * u4.y + x.z * u4.z + x.w * u4.w;
        #pragma unroll
        for (int o = 16; o > 0; o >>= 1)
            dsum += __shfl_xor_sync(0xffffffffu, dsum, o);
        if (lane == 0) g_nb[j] = dsum + sconsts;
    }
}

// ---------------------------------------------------------------------------
// Main: one block per row, 1024 threads, CLC overlap at row boundaries.
// Warp w owns j in [w*32, w*32+32), unroll 8.
// New vs R5: (a) exp tail parallelized across lanes (post-butterfly all
// lanes hold d0..d7; lane selects lane&7, shuffles its nb from a preloaded
// register, one expf per lane); (b) nb loads hoisted out of the loop;
// (c) single-barrier epilogue (every warp reduces all 32 partials itself).
// ---------------------------------------------------------------------------
__global__ void __launch_bounds__(1024, 1)
main_kernel(const float* __restrict__ edge_feat, float* __restrict__ out) {
    const int i    = blockIdx.x;
    const int tid  = threadIdx.x;
    const int lane = tid & 31;
    const int w    = tid >> 5;

    __shared__ float sp[N];      // exp(energy)
    __shared__ float sred[32];

    const float4 v4 = reinterpret_cast<const float4*>(g_v)[lane];
    const float4* base =
        reinterpret_cast<const float4*>(edge_feat + (size_t)i * N * D);

    const int j0 = w << 5;
    const float nbv = g_nb[j0 + lane];   // this warp's 32 nb values, coalesced
    const int sel = lane & 7;

    float wsum = 0.f;
    #pragma unroll
    for (int k = 0; k < 32; k += 8) {
        float4 x0 = __ldcs(&base[(size_t)(j0 + k + 0) * (D / 4) + lane]);
        float4 x1 = __ldcs(&base[(size_t)(j0 + k + 1) * (D / 4) + lane]);
        float4 x2 = __ldcs(&base[(size_t)(j0 + k + 2) * (D / 4) + lane]);
        float4 x3 = __ldcs(&base[(size_t)(j0 + k + 3) * (D / 4) + lane]);
        float4 x4 = __ldcs(&base[(size_t)(j0 + k + 4) * (D / 4) + lane]);
        float4 x5 = __ldcs(&base[(size_t)(j0 + k + 5) * (D / 4) + lane]);
        float4 x6 = __ldcs(&base[(size_t)(j0 + k + 6) * (D / 4) + lane]);
        float4 x7 = __ldcs(&base[(size_t)(j0 + k + 7) * (D / 4) + lane]);
        float d0 = x0.x * v4.x + x0.y * v4.y + x0.z * v4.z + x0.w * v4.w;
        float d1 = x1.x * v4.x + x1.y * v4.y + x1.z * v4.z + x1.w * v4.w;
        float d2 = x2.x * v4.x + x2.y * v4.y + x2.z * v4.z + x2.w * v4.w;
        float d3 = x3.x * v4.x + x3.y * v4.y + x3.z * v4.z + x3.w * v4.w;
        float d4 = x4.x * v4.x + x4.y * v4.y + x4.z * v4.z + x4.w * v4.w;
        float d5 = x5.x * v4.x + x5.y * v4.y + x5.z * v4.z + x5.w * v4.w;
        float d6 = x6.x * v4.x + x6.y * v4.y + x6.z * v4.z + x6.w * v4.w;
        float d7 = x7.x * v4.x + x7.y * v4.y + x7.z * v4.z + x7.w * v4.w;
        #pragma unroll
        for (int o = 16; o > 0; o >>= 1) {
            d0 += __shfl_xor_sync(0xffffffffu, d0, o);
            d1 += __shfl_xor_sync(0xffffffffu, d1, o);
            d2 += __shfl_xor_sync(0xffffffffu, d2, o);
            d3 += __shfl_xor_sync(0xffffffffu, d3, o);
            d4 += __shfl_xor_sync(0xffffffffu, d4, o);
            d5 += __shfl_xor_sync(0xffffffffu, d5, o);
            d6 += __shfl_xor_sync(0xffffffffu, d6, o);
            d7 += __shfl_xor_sync(0xffffffffu, d7, o);
        }
        // all lanes hold full sums d0..d7 now; pick lane&7's value
        float dv = d0;
        dv = (sel == 1) ? d1 : dv;
        dv = (sel == 2) ? d2 : dv;
        dv = (sel == 3) ? d3 : dv;
        dv = (sel == 4) ? d4 : dv;
        dv = (sel == 5) ? d5 : dv;
        dv = (sel == 6) ? d6 : dv;
        dv = (sel == 7) ? d7 : dv;
        float nb = __shfl_sync(0xffffffffu, nbv, k + sel);
        float p  = __expf(dv + nb);
        if (lane < 8) {
            sp[j0 + k + lane] = p;
            wsum += p;
        }
    }
    // lanes >=8 carry wsum = 0; full butterfly gives warp total on all lanes
    #pragma unroll
    for (int o = 16; o > 0; o >>= 1)
        wsum += __shfl_xor_sync(0xffffffffu, wsum, o);
    if (lane == 0) sred[w] = wsum;
    __syncthreads();   // single barrier

    // every warp reduces all 32 partials itself (no second barrier)
    float ss = sred[lane];
    #pragma unroll
    for (int o = 16; o > 0; o >>= 1)
        ss += __shfl_xor_sync(0xffffffffu, ss, o);

    out[(size_t)i * N + tid] = sp[tid] * (1.0f / ss);
}

// ---------------------------------------------------------------------------
// Launcher. Input order per metadata:
// 0 node_feat (N,D) f32 | 1 edge_feat (N,N,D) f32 | 2 mask (unused)
// 3 Wh | 4 bh | 5 Wt | 6 bt | 7 Wr | 8 br | 9 wt_w | 10 wt_b
// ---------------------------------------------------------------------------
extern "C" void kernel_launch(void* const* d_in, const int* in_sizes, int n_in,
                              void* d_out, int out_size) {
    const float* node_feat = (const float*)d_in[0];
    const float* edge_feat = (const float*)d_in[1];
    const float* Wh   = (const float*)d_in[3];
    const float* bh   = (const float*)d_in[4];
    const float* Wt   = (const float*)d_in[5];
    const float* bt   = (const float*)d_in[6];
    const float* Wr   = (const float*)d_in[7];
    const float* br   = (const float*)d_in[8];
    const float* wt_w = (const float*)d_in[9];
    const float* wt_b = (const float*)d_in[10];
    float* out = (float*)d_out;

    prologue_kernel<<<128, 1024>>>(node_feat, Wh, bh, Wt, bt, Wr, br, wt_w, wt_b);
    main_kernel<<<N, 1024>>>(edge_feat, out);
}

// round 9
// speedup vs baseline: 1.0429x; 1.0026x over previous
#include <cuda_runtime.h>
#include <cuda_bf16.h>

#define N 1024
#define D 128
#define H 128

// Scratch (allocation-free rule: __device__ globals)
__device__ __align__(16) float g_v[D];   // reduced v
__device__ float g_nb[N];                // node_part[j] + consts

// ---------------------------------------------------------------------------
// Prologue (fused setup + nodepart). 128 blocks x 1024 threads. (verified)
// ---------------------------------------------------------------------------
__global__ void __launch_bounds__(1024, 1)
prologue_kernel(const float* __restrict__ node_feat,
                const float* __restrict__ Wh,
                const float* __restrict__ bh,
                const float* __restrict__ Wt,
                const float* __restrict__ bt,
                const float* __restrict__ Wr,
                const float* __restrict__ br,
                const float* __restrict__ wt_w,
                const float* __restrict__ wt_b) {
    const int tid  = threadIdx.x;
    const int d    = tid & 127;
    const int g    = tid >> 7;      // 0..7
    const int lane = tid & 31;
    const int w    = tid >> 5;      // warp 0..31

    __shared__ float su[8][128];
    __shared__ float sv[8][128];
    __shared__ float sconsts;

    float u = 0.f, v = 0.f;
    const int h0 = g * 16;
    #pragma unroll
    for (int k = 0; k < 16; ++k) {
        int h = h0 + k;
        float w1 = __ldg(&wt_w[h]);
        float w2 = __ldg(&wt_w[H + h]);
        float w3 = __ldg(&wt_w[2 * H + h]);
        u = fmaf(__ldg(&Wh[h * D + d]), w1, u);
        u = fmaf(__ldg(&Wt[h * D + d]), w2, u);
        v = fmaf(__ldg(&Wr[h * D + d]), w3, v);
    }
    su[g][d] = u;
    sv[g][d] = v;

    if (tid < 32) {
        float c = 0.f;
        #pragma unroll
        for (int h = lane; h < H; h += 32) {
            c += bh[h] * __ldg(&wt_w[h]) + bt[h] * __ldg(&wt_w[H + h]) +
                 br[h] * __ldg(&wt_w[2 * H + h]);
        }
        #pragma unroll
        for (int o = 16; o > 0; o >>= 1) c += __shfl_xor_sync(0xffffffffu, c, o);
        if (lane == 0) sconsts = c + __ldg(&wt_b[0]);
    }
    __syncthreads();

    if (blockIdx.x == 0 && tid < 128) {
        float vv = 0.f;
        #pragma unroll
        for (int gg = 0; gg < 8; ++gg) vv += sv[gg][tid];
        g_v[tid] = vv;
    }

    if (w < 8) {
        const int j = blockIdx.x * 8 + w;
        float4 u4 = make_float4(0.f, 0.f, 0.f, 0.f);
        #pragma unroll
        for (int gg = 0; gg < 8; ++gg) {
            float4 p = reinterpret_cast<const float4*>(su[gg])[lane];
            u4.x += p.x; u4.y += p.y; u4.z += p.z; u4.w += p.w;
        }
        float4 x = reinterpret_cast<const float4*>(node_feat + (size_t)j * D)[lane];
        float dsum = x.x * u4.x + x.y * u4.y + x.z * u4.z + x.w * u4.w;
        #pragma unroll
        for (int o = 16; o > 0; o >>= 1)
            dsum += __shfl_xor_sync(0xffffffffu, dsum, o);
        if (lane == 0) g_nb[j] = dsum + sconsts;
    }
}

// Merge two distributed partial sums: lanes with (lane&bit)==0 end up with
// the pair-sum of 'a', lanes with bit set get the pair-sum of 'b'.
// 1 SHFL + 2 SEL (vs 2 SHFL for two independent butterflies at this stage).
__device__ __forceinline__ float merge2(float a, float b, int lane, int bit) {
    float t = (lane & bit) ? a : b;                   // send the partner's value
    float u = __shfl_xor_sync(0xffffffffu, t, bit);
    return ((lane & bit) ? b : a) + u;
}

// ---------------------------------------------------------------------------
// Main: one block per row, 1024 threads, CLC overlap at row boundaries.
// Warp w owns j in [w*32, w*32+32), unroll 8.
// New vs R8: merge-tree reduction — 9 SHFL per 8-j batch instead of 40,
// cutting MIO-pipe pressure ~4x so SHFL traffic stops throttling LDG issue.
// After the tree, lane holds full sum of d[idx], idx = b2<<2 | b3<<1 | b4.
// ---------------------------------------------------------------------------
__global__ void __launch_bounds__(1024, 1)
main_kernel(const float* __restrict__ edge_feat, float* __restrict__ out) {
    const int i    = blockIdx.x;
    const int tid  = threadIdx.x;
    const int lane = tid & 31;
    const int w    = tid >> 5;

    __shared__ float sp[N];      // exp(energy)
    __shared__ float sred[32];

    const float4 v4 = reinterpret_cast<const float4*>(g_v)[lane];
    const float4* base =
        reinterpret_cast<const float4*>(edge_feat + (size_t)i * N * D);

    const int j0 = w << 5;
    const float nbv = g_nb[j0 + lane];   // this warp's 32 nb values, coalesced
    const int idx = (((lane >> 2) & 1) << 2) | (((lane >> 3) & 1) << 1)
                  | ((lane >> 4) & 1);   // which d this lane ends up owning

    float wsum = 0.f;
    #pragma unroll
    for (int k = 0; k < 32; k += 8) {
        float4 x0 = __ldcs(&base[(size_t)(j0 + k + 0) * (D / 4) + lane]);
        float4 x1 = __ldcs(&base[(size_t)(j0 + k + 1) * (D / 4) + lane]);
        float4 x2 = __ldcs(&base[(size_t)(j0 + k + 2) * (D / 4) + lane]);
        float4 x3 = __ldcs(&base[(size_t)(j0 + k + 3) * (D / 4) + lane]);
        float4 x4 = __ldcs(&base[(size_t)(j0 + k + 4) * (D / 4) + lane]);
        float4 x5 = __ldcs(&base[(size_t)(j0 + k + 5) * (D / 4) + lane]);
        float4 x6 = __ldcs(&base[(size_t)(j0 + k + 6) * (D / 4) + lane]);
        float4 x7 = __ldcs(&base[(size_t)(j0 + k + 7) * (D / 4) + lane]);
        float d0 = x0.x * v4.x + x0.y * v4.y + x0.z * v4.z + x0.w * v4.w;
        float d1 = x1.x * v4.x + x1.y * v4.y + x1.z * v4.z + x1.w * v4.w;
        float d2 = x2.x * v4.x + x2.y * v4.y + x2.z * v4.z + x2.w * v4.w;
        float d3 = x3.x * v4.x + x3.y * v4.y + x3.z * v4.z + x3.w * v4.w;
        float d4 = x4.x * v4.x + x4.y * v4.y + x4.z * v4.z + x4.w * v4.w;
        float d5 = x5.x * v4.x + x5.y * v4.y + x5.z * v4.z + x5.w * v4.w;
        float d6 = x6.x * v4.x + x6.y * v4.y + x6.z * v4.z + x6.w * v4.w;
        float d7 = x7.x * v4.x + x7.y * v4.y + x7.z * v4.z + x7.w * v4.w;

        // merge tree: 8 values -> 1 per lane group. 9 SHFLs total.
        float e0 = merge2(d0, d1, lane, 16);
        float e1 = merge2(d2, d3, lane, 16);
        float e2 = merge2(d4, d5, lane, 16);
        float e3 = merge2(d6, d7, lane, 16);
        float f0 = merge2(e0, e1, lane, 8);
        float f1 = merge2(e2, e3, lane, 8);
        float gg = merge2(f0, f1, lane, 4);
        gg += __shfl_xor_sync(0xffffffffu, gg, 2);
        gg += __shfl_xor_sync(0xffffffffu, gg, 1);
        // lane now holds full dot for j = j0 + k + idx (4 lanes per value)

        float nb = __shfl_sync(0xffffffffu, nbv, k + idx);
        float p  = __expf(gg + nb);
        if ((lane & 3) == 0) {
            sp[j0 + k + idx] = p;
            wsum += p;
        }
    }
    // 8 storing lanes hold distinct values; others carry 0
    #pragma unroll
    for (int o = 16; o > 0; o >>= 1)
        wsum += __shfl_xor_sync(0xffffffffu, wsum, o);
    if (lane == 0) sred[w] = wsum;
    __syncthreads();   // single barrier

    float ss = sred[lane];
    #pragma unroll
    for (int o = 16; o > 0; o >>= 1)
        ss += __shfl_xor_sync(0xffffffffu, ss, o);

    out[(size_t)i * N + tid] = sp[tid] * (1.0f / ss);
}

// ---------------------------------------------------------------------------
// Launcher. Input order per metadata:
// 0 node_feat (N,D) f32 | 1 edge_feat (N,N,D) f32 | 2 mask (unused)
// 3 Wh | 4 bh | 5 Wt | 6 bt | 7 Wr | 8 br | 9 wt_w | 10 wt_b
// ---------------------------------------------------------------------------
extern "C" void kernel_launch(void* const* d_in, const int* in_sizes, int n_in,
                              void* d_out, int out_size) {
    const float* node_feat = (const float*)d_in[0];
    const float* edge_feat = (const float*)d_in[1];
    const float* Wh   = (const float*)d_in[3];
    const float* bh   = (const float*)d_in[4];
    const float* Wt   = (const float*)d_in[5];
    const float* bt   = (const float*)d_in[6];
    const float* Wr   = (const float*)d_in[7];
    const float* br   = (const float*)d_in[8];
    const float* wt_w = (const float*)d_in[9];
    const float* wt_b = (const float*)d_in[10];
    float* out = (float*)d_out;

    prologue_kernel<<<128, 1024>>>(node_feat, Wh, bh, Wt, bt, Wr, br, wt_w, wt_b);
    main_kernel<<<N, 1024>>>(edge_feat, out);
}